// round 13
// baseline (speedup 1.0000x reference)
#include <cuda_runtime.h>

// LoCon1d: out[b][o][s] = bias[o][s] + sum_{c,k} in[b][c][s+k-1] * w[o][c][s][k]
// input (16,64,1024), weight (64,64,1024,3), bias (64,1024), out (16,64,1024), f32.
//
// Grid 256 = 128 s-tiles x 2 o-halves; CTA = 32 couts x 8 s x 16 b, full c-reduction.
// Input tile transposed into smem (swizzled, conflict-free LDS.128 across rows).
// Weight slab (32o x 24 floats per c) staged densely via float4 LDG -> linear STS,
// consumed as conflict-free scalar LDS. Math: packed fp32x2 FMA.

#define CIN   64
#define COUT  64
#define SLEN  1024
#define BATCH 16
#define SP    8
#define JROWS 10
#define TPB   256
#define OH    32          // couts per CTA

typedef unsigned long long ull;

__device__ __forceinline__ ull pack2(float w) {
    ull r; asm("mov.b64 %0, {%1, %1};" : "=l"(r) : "f"(w)); return r;
}
__device__ __forceinline__ void fma2(ull& a, ull x, ull w) {
    asm("fma.rn.f32x2 %0, %1, %2, %0;" : "+l"(a) : "l"(x), "l"(w));
}
__device__ __forceinline__ float2 unpack2(ull a) {
    float2 f; asm("mov.b64 {%0, %1}, %2;" : "=f"(f.x), "=f"(f.y) : "l"(a)); return f;
}

__global__ __launch_bounds__(TPB)
void locon_kernel(const float* __restrict__ input,
                  const float* __restrict__ weight,
                  const float* __restrict__ bias,
                  float* __restrict__ out)
{
    __shared__ float sm[CIN * JROWS * BATCH];  // 40960 B input tile
    __shared__ float ws[OH * 24];              // 3072 B weight slab (one c)

    const int tid = threadIdx.x;
    const int s0  = blockIdx.x * SP;
    const int o0  = blockIdx.y * OH;

    // ---- weight staging plumbing: 192 tasks = 32 o x 6 float4-pieces ----
    const bool wt = tid < 192;
    const int  ol = tid / 6;
    const int  pc = tid % 6;
    const float* wsrc = weight + (((size_t)(o0 + ol) * CIN) * SLEN + s0) * 3 + pc * 4;
    // per-c advance: SLEN*3 floats

    float4 r0, rA, rB;
    if (wt) {
        r0 = *(const float4*)(wsrc);                           // slab 0
        rA = *(const float4*)(wsrc + (size_t)1 * SLEN * 3);    // slab 1
        rB = *(const float4*)(wsrc + (size_t)2 * SLEN * 3);    // slab 2
    }

    // ---- fill: transpose input tile into smem (coalesced float4 along s) ----
#pragma unroll
    for (int it = 0; it < 16; it++) {
        const int chunk = tid & 3;
        const int row   = it * (TPB / 4) + (tid >> 2);
        const int b = row & 15, c = row >> 4;
        const int bg = b >> 2, bsub = b & 3;
        const float* gin = input + ((size_t)b * CIN + c) * SLEN;
        if (chunk == 1 || chunk == 2) {
            const float4 v = *(const float4*)(gin + s0 - 4 + chunk * 4);
            const float vv[4] = { v.x, v.y, v.z, v.w };
#pragma unroll
            for (int e = 0; e < 4; e++) {
                const int j = chunk * 4 - 3 + e;          // 1..4 or 5..8
                const int slot = ((bg + (j >> 1)) & 3) * 4 + bsub;
                sm[(c * JROWS + j) * BATCH + slot] = vv[e];
            }
        } else if (chunk == 0) {                          // j = 0, gs = s0-1
            const int gs = s0 - 1;
            const float v = (gs >= 0) ? gin[gs] : 0.0f;
            sm[(c * JROWS + 0) * BATCH + (bg & 3) * 4 + bsub] = v;
        } else {                                          // j = 9, gs = s0+8
            const int gs = s0 + 8;
            const float v = (gs < SLEN) ? gin[gs] : 0.0f;
            sm[(c * JROWS + 9) * BATCH + (bg & 3) * 4 + bsub] = v;
        }
    }

    if (wt) *(float4*)(ws + ol * 24 + pc * 4) = r0;       // stage slab 0
    __syncthreads();

    // ---- compute: thread = (o, s), all 16 batches ----
    const int olc = tid >> 3;           // local cout
    const int s   = tid & 7;            // local s
    const int sg  = s0 + s;
    const int o   = o0 + olc;

    ull acc[8];
#pragma unroll
    for (int i = 0; i < 8; i++) acc[i] = 0ULL;

    const float* wq = ws + olc * 24 + s * 3;

    for (int c = 0; c < CIN; c++) {
        const float w0 = wq[0], w1 = wq[1], w2 = wq[2];   // conflict-free LDS
        const ull W[3] = { pack2(w0), pack2(w1), pack2(w2) };

        const float* base = sm + c * (JROWS * BATCH);
#pragma unroll
        for (int k = 0; k < 3; k++) {
            const int j = s + k;
            const float* rowb = base + j * BATCH;
            const int half = j >> 1;
            const ull Wk = W[k];
#pragma unroll
            for (int i = 0; i < 4; i++) {
                const ulonglong2 v =
                    *(const ulonglong2*)(rowb + ((i + half) & 3) * 4);
                fma2(acc[2 * i],     v.x, Wk);
                fma2(acc[2 * i + 1], v.y, Wk);
            }
        }

        __syncthreads();                 // everyone done reading slab c
        if (wt) {
            if (c < CIN - 1) *(float4*)(ws + ol * 24 + pc * 4) = rA;  // slab c+1
            rA = rB;
            if (c + 3 < CIN) rB = *(const float4*)(wsrc + (size_t)(c + 3) * SLEN * 3);
        }
        __syncthreads();                 // slab c+1 visible
    }

    // ---- bias + store ----
    const float bv = bias[(size_t)o * SLEN + sg];
#pragma unroll
    for (int i = 0; i < 4; i++) {
        const float2 lo = unpack2(acc[2 * i]);
        const float2 hi = unpack2(acc[2 * i + 1]);
        const int b0 = 4 * i;
        out[((size_t)(b0 + 0) * COUT + o) * SLEN + sg] = lo.x + bv;
        out[((size_t)(b0 + 1) * COUT + o) * SLEN + sg] = lo.y + bv;
        out[((size_t)(b0 + 2) * COUT + o) * SLEN + sg] = hi.x + bv;
        out[((size_t)(b0 + 3) * COUT + o) * SLEN + sg] = hi.y + bv;
    }
}

extern "C" void kernel_launch(void* const* d_in, const int* in_sizes, int n_in,
                              void* d_out, int out_size)
{
    const float* input  = (const float*)d_in[0];  // (16, 64, 1024)
    const float* weight = (const float*)d_in[1];  // (64, 64, 1024, 3)
    const float* bias   = (const float*)d_in[2];  // (64, 1024)
    float* out = (float*)d_out;                   // (16, 64, 1024)

    dim3 grid(SLEN / SP, COUT / OH);   // 128 x 2 = 256 CTAs, 256 thr
    locon_kernel<<<grid, TPB>>>(input, weight, bias, out);
}